// round 17
// baseline (speedup 1.0000x reference)
#include <cuda_runtime.h>
#include <cstdint>

#define N_PULSES 64
#define N_STATES 21
#define BPW 12

typedef unsigned long long u64;

__device__ __forceinline__ u64 pk(float lo, float hi) {
    u64 r; asm("mov.b64 %0,{%1,%2};" : "=l"(r) : "f"(lo), "f"(hi)); return r;
}
__device__ __forceinline__ void upk(u64 v, float& lo, float& hi) {
    asm("mov.b64 {%0,%1},%2;" : "=f"(lo), "=f"(hi) : "l"(v));
}
__device__ __forceinline__ float lof(u64 v) { float a,b; upk(v,a,b); return a; }
__device__ __forceinline__ float hif(u64 v) { float a,b; upk(v,a,b); return b; }
__device__ __forceinline__ u64 fma2(u64 a, u64 b, u64 c) {
    u64 d; asm("fma.rn.f32x2 %0,%1,%2,%3;" : "=l"(d) : "l"(a), "l"(b), "l"(c)); return d;
}
__device__ __forceinline__ u64 mul2(u64 a, u64 b) {
    u64 d; asm("mul.rn.f32x2 %0,%1,%2;" : "=l"(d) : "l"(a), "l"(b)); return d;
}
__device__ __forceinline__ float4 f4of(u64 a, u64 b) {
    float4 v; upk(a, v.x, v.y); upk(b, v.z, v.w); return v;
}
__device__ __forceinline__ float read_scalar(const void* p) {
    int iv = *(const int*)p;
    if (iv > 0 && iv < 1000000) return (float)iv;
    return *(const float*)p;
}
__device__ __forceinline__ void fill_tp(u64 (*s_tp)[8], const float* flip,
                                        const float* phases, int tid) {
    if (tid < N_PULSES) {
        float b = phases[tid], sb, cb;
        sincosf(b, &sb, &cb);
        float c2b = cb*cb - sb*sb, s2b = 2.0f*cb*sb;
        s_tp[tid][0]=pk(cb,cb);   s_tp[tid][1]=pk(c2b,c2b); s_tp[tid][2]=pk(s2b,s2b);
        s_tp[tid][3]=pk(-sb,-sb); s_tp[tid][4]=pk(-cb,-cb); s_tp[tid][5]=pk(-c2b,-c2b);
        s_tp[tid][6]=pk(-s2b,-s2b); s_tp[tid][7]=pk(flip[tid],flip[tid]);
    }
}

// MAIN: slot layout. Lane l owns slots 8l..8l+7 (slot=lbatch*21+state) of a
// 12-batch group as 4 f32x2 columns. Requires nbatch % 4 == 0.
__global__ __launch_bounds__(128, 3)
void epg_main(const float* __restrict__ flip, const float* __restrict__ phases,
              const float* __restrict__ T1, const float* __restrict__ T2,
              const float* __restrict__ B0, const float* __restrict__ B1,
              const void* __restrict__ TRp, float* __restrict__ out,
              int nbatch, int nwarps)
{
    __shared__ u64 s_tp[N_PULSES][8];
    const int tid = threadIdx.x;
    fill_tp(s_tp, flip, phases, tid);
    __syncthreads();

    const int lane = tid & 31;
    const int wid  = blockIdx.x * 4 + (tid >> 5);
    if (wid >= nwarps) return;
    const int base = wid * BPW;
    const size_t cs = (size_t)nbatch * N_STATES;

    const float TR = read_scalar(TRp);
    const float TPM = 2.0f * 3.14159265358979f * 0.001f;

    const int sA = 8 * lane;
    const int bA = sA / 21, bB = (sA + 7) / 21;
    const int lastb = nbatch - 1;
    const int gA = (base + bA < nbatch) ? base + bA : lastb;
    const int gB = (base + bB < nbatch) ? base + bB : lastb;

    const float E1A = expf(-TR/T1[gA]), E1B = expf(-TR/T1[gB]);
    const float E2A = expf(-TR/T2[gA]), E2B = expf(-TR/T2[gB]);
    float spA,cpA,spB,cpB;
    sincosf(TPM*B0[gA]*TR, &spA, &cpA);
    sincosf(TPM*B0[gB]*TR, &spB, &cpB);
    const float crA = E2A*cpA, ciA = E2A*spA, crB = E2B*cpB, ciB = E2B*spB;
    const float zmA = 1.0f - E1A, zmB = 1.0f - E1B;
    const float b1A = 0.5f*B1[gA], b1B = 0.5f*B1[gB];

#define MKCOL(c)                                                               \
    const int  lo##c = sA + 2*(c), hi##c = lo##c + 1;                          \
    const bool la##c = (lo##c / 21 == bA), ha##c = (hi##c / 21 == bA);         \
    const u64 E1p##c  = pk(la##c?E1A:E1B,  ha##c?E1A:E1B);                     \
    const u64 cpr##c  = pk(la##c?crA:crB,  ha##c?crA:crB);                     \
    const u64 cpi##c  = pk(la##c?ciA:ciB,  ha##c?ciA:ciB);                     \
    const u64 cpin##c = pk(la##c?-ciA:-ciB, ha##c?-ciA:-ciB);                  \
    const u64 zadd##c = pk((lo##c%21==0) ? (la##c?zmA:zmB) : 0.0f,             \
                           (hi##c%21==0) ? (ha##c?zmA:zmB) : 0.0f);            \
    const u64 mFp##c  = pk((lo##c%21==0)?0.0f:1.0f, (hi##c%21==0)?0.0f:1.0f);  \
    const u64 mFm##c  = pk((lo##c%21==20)?0.0f:1.0f,(hi##c%21==20)?0.0f:1.0f); \
    u64 Zs##c  = pk((lo##c%21==0)?1.0f:0.0f, (hi##c%21==0)?1.0f:0.0f);         \
    u64 Fpr##c = 0ull, Fpi##c = 0ull, Fmr##c = 0ull, Fmi##c = 0ull;
    MKCOL(0) MKCOL(1) MKCOL(2) MKCOL(3)
#undef MKCOL

    const u64 m1p = pk(-1.0f,-1.0f), m2p = pk(-2.0f,-2.0f), onep = pk(1.0f,1.0f);

    // Store predicates for (possibly partial) last group
    const int grem = nbatch - base;
    const int vf = ((grem < BPW) ? grem : BPW) * N_STATES;   // valid floats
    const bool q1 = (sA + 4 <= vf), q2 = (sA + 8 <= vf);
    float* op = out + (size_t)base * N_STATES + sA;

#define ADV(c)                                                                 \
    u64 pR##c, pI##c, mR##c, mI##c;                                            \
    {                                                                          \
        const u64 zr  = fma2(E1p##c, Zs##c, zadd##c);                          \
        const u64 npr = fma2(cpr##c, Fpr##c, mul2(cpin##c, Fpi##c));           \
        const u64 npi = fma2(cpr##c, Fpi##c, mul2(cpi##c,  Fpr##c));           \
        const u64 nmr = fma2(cpr##c, Fmr##c, mul2(cpi##c,  Fmi##c));           \
        const u64 nmi = fma2(cpr##c, Fmi##c, mul2(cpin##c, Fmr##c));           \
        const u64 ca2p = fma2(sa2##c, m1p, onep);                              \
        const u64 k7   = fma2(sa2##c, m2p, onep);                              \
        const u64 k1  = mul2(sa2##c, tp1);                                     \
        const u64 k2  = mul2(sa2##c, tp2);                                     \
        const u64 k1n = mul2(sa2##c, tp5);                                     \
        const u64 k2n = mul2(sa2##c, tp6);                                     \
        const u64 k3n = mul2(csa##c, tp3);                                     \
        const u64 k4  = mul2(csa##c, tp0);                                     \
        const u64 k4n = mul2(csa##c, tp4);                                     \
        pR##c = fma2(k3n, zr, fma2(k2,  nmi, fma2(k1,  nmr, mul2(ca2p, npr))));\
        pI##c = fma2(k4,  zr, fma2(k1n, nmi, fma2(k2,  nmr, mul2(ca2p, npi))));\
        mR##c = fma2(k3n, zr, fma2(ca2p, nmr, fma2(k2n, npi, mul2(k1, npr)))); \
        mI##c = fma2(k4n, zr, fma2(ca2p, nmi, fma2(k1n, npi, mul2(k2n, npr))));\
        Zs##c = fma2(k7,  zr, fma2(k3n, nmr, fma2(k3n, npr,                    \
                                  fma2(k4n, nmi, mul2(k4, npi)))));            \
    }

#pragma unroll 1
    for (int t = 0; t < N_PULSES; ++t) {
        const u64* tp = s_tp[t];
        const u64 tp0=tp[0], tp1=tp[1], tp2=tp[2], tp3=tp[3];
        const u64 tp4=tp[4], tp5=tp[5], tp6=tp[6];
        const float af = lof(tp[7]);

        float saA,caA,saB,caB;
        __sincosf(af*b1A, &saA, &caA);
        __sincosf(af*b1B, &saB, &caB);
        const float s2A=saA*saA, xA=caA*saA, s2B=saB*saB, xB=caB*saB;
#define MKRF(c) const u64 sa2##c = pk(la##c?s2A:s2B, ha##c?s2A:s2B);           \
                const u64 csa##c = pk(la##c?xA:xB,  ha##c?xA:xB);
        MKRF(0) MKRF(1) MKRF(2) MKRF(3)
#undef MKRF

        ADV(0) ADV(1) ADV(2) ADV(3)

        // Fp shift up: new slot s = old s-1 (zero at state 0). Carry from lane-1.
        {
            const float cR = __shfl_up_sync(0xffffffffu, hif(pR3), 1);
            const float cI = __shfl_up_sync(0xffffffffu, hif(pI3), 1);
            Fpr0 = mul2(pk(cR,       lof(pR0)), mFp0);
            Fpr1 = mul2(pk(hif(pR0), lof(pR1)), mFp1);
            Fpr2 = mul2(pk(hif(pR1), lof(pR2)), mFp2);
            Fpr3 = mul2(pk(hif(pR2), lof(pR3)), mFp3);
            Fpi0 = mul2(pk(cI,       lof(pI0)), mFp0);
            Fpi1 = mul2(pk(hif(pI0), lof(pI1)), mFp1);
            Fpi2 = mul2(pk(hif(pI1), lof(pI2)), mFp2);
            Fpi3 = mul2(pk(hif(pI2), lof(pI3)), mFp3);
        }
        // Fm shift down: new slot s = old s+1 (zero at state 20). Carry from lane+1.
        {
            const float cR = __shfl_down_sync(0xffffffffu, lof(mR0), 1);
            const float cI = __shfl_down_sync(0xffffffffu, lof(mI0), 1);
            Fmr0 = mul2(pk(hif(mR0), lof(mR1)), mFm0);
            Fmr1 = mul2(pk(hif(mR1), lof(mR2)), mFm1);
            Fmr2 = mul2(pk(hif(mR2), lof(mR3)), mFm2);
            Fmr3 = mul2(pk(hif(mR3), cR),       mFm3);
            Fmi0 = mul2(pk(hif(mI0), lof(mI1)), mFm0);
            Fmi1 = mul2(pk(hif(mI1), lof(mI2)), mFm1);
            Fmi2 = mul2(pk(hif(mI2), lof(mI3)), mFm2);
            Fmi3 = mul2(pk(hif(mI3), cI),       mFm3);
        }

        // Wide coalesced stores: 2 x STG.128 per component (predicated)
        {
            float4* q0 = (float4*)(op);
            float4* q1p = (float4*)(op + cs);
            float4* q2p = (float4*)(op + 2*cs);
            float4* q3p = (float4*)(op + 3*cs);
            float4* q4p = (float4*)(op + 4*cs);
            if (q1) { __stcs(q0,  f4of(Fpr0,Fpr1)); __stcs(q1p, f4of(Fpi0,Fpi1));
                      __stcs(q2p, f4of(Fmr0,Fmr1)); __stcs(q3p, f4of(Fmi0,Fmi1));
                      __stcs(q4p, f4of(Zs0, Zs1)); }
            if (q2) { __stcs(q0+1,  f4of(Fpr2,Fpr3)); __stcs(q1p+1, f4of(Fpi2,Fpi3));
                      __stcs(q2p+1, f4of(Fmr2,Fmr3)); __stcs(q3p+1, f4of(Fmi2,Fmi3));
                      __stcs(q4p+1, f4of(Zs2, Zs3)); }
        }
        op += 5 * cs;
    }
#undef ADV
}

// FALLBACK (nbatch % 4 != 0): warp per batch, lane = state, scalar math.
__global__ __launch_bounds__(256)
void epg_simple(const float* __restrict__ flip, const float* __restrict__ phases,
                const float* __restrict__ T1, const float* __restrict__ T2,
                const float* __restrict__ B0, const float* __restrict__ B1,
                const void* __restrict__ TRp, float* __restrict__ out, int nbatch)
{
    const int lane = threadIdx.x & 31;
    const int b = blockIdx.x * 8 + (threadIdx.x >> 5);
    if (b >= nbatch) return;
    const float TR = read_scalar(TRp);
    const float E1 = expf(-TR/T1[b]), E2 = expf(-TR/T2[b]);
    float sp, cp;
    sincosf(2.0f*3.14159265358979f*0.001f*B0[b]*TR, &sp, &cp);
    const float cr = E2*cp, ci = E2*sp;
    const float b1h = 0.5f*B1[b];
    const float zadd = (lane==0) ? 1.0f-E1 : 0.0f;
    float Fpr=0, Fpi=0, Fmr=0, Fmi=0, Z = (lane==0)?1.0f:0.0f;
    const size_t cs = (size_t)nbatch * N_STATES;
    float* o = out + (size_t)b * N_STATES + lane;
    const bool act = lane < N_STATES;
    for (int t = 0; t < N_PULSES; ++t) {
        float sb, cb;
        sincosf(phases[t], &sb, &cb);
        float c2b = cb*cb - sb*sb, s2b = 2.0f*cb*sb;
        float zr = E1*Z + zadd;
        float npr = cr*Fpr - ci*Fpi, npi = cr*Fpi + ci*Fpr;
        float nmr = cr*Fmr + ci*Fmi, nmi = cr*Fmi - ci*Fmr;
        float sa, ca;
        __sincosf(flip[t]*b1h, &sa, &ca);
        float ca2 = ca*ca, sa2 = sa*sa, cs_ = ca*sa;
        float k1 = sa2*c2b, k2 = sa2*s2b, k3 = cs_*sb, k4 = cs_*cb, k7 = ca2-sa2;
        float pr = ca2*npr + k1*nmr + k2*nmi - k3*zr;
        float pi = ca2*npi + k2*nmr - k1*nmi + k4*zr;
        float mr = k1*npr - k2*npi + ca2*nmr - k3*zr;
        float mi = -k2*npr - k1*npi + ca2*nmi - k4*zr;
        float zn = k4*(npi-nmi) - k3*(npr+nmr) + k7*zr;
        float sr = __shfl_up_sync(0xffffffffu, pr, 1);
        float si = __shfl_up_sync(0xffffffffu, pi, 1);
        float tr_ = __shfl_down_sync(0xffffffffu, mr, 1);
        float ti = __shfl_down_sync(0xffffffffu, mi, 1);
        if (lane == 0 || lane >= N_STATES) { sr = 0; si = 0; }
        if (lane >= N_STATES-1) { tr_ = 0; ti = 0; }
        Fpr = sr; Fpi = si; Fmr = tr_; Fmi = ti; Z = zn;
        if (act) {
            float* ot = o + (size_t)t*5u*cs;
            ot[0]=Fpr; ot[cs]=Fpi; ot[2*cs]=Fmr; ot[3*cs]=Fmi; ot[4*cs]=zn;
        }
    }
}

extern "C" void kernel_launch(void* const* d_in, const int* in_sizes, int n_in,
                              void* d_out, int out_size)
{
    const float* flip   = (const float*)d_in[0];
    const float* phases = (const float*)d_in[1];
    const float* T1     = (const float*)d_in[2];
    const float* T2     = (const float*)d_in[3];
    const float* B0     = (const float*)d_in[4];
    const float* B1     = (const float*)d_in[5];
    const void*  TRp    = d_in[6];
    const int nbatch = in_sizes[2];
    float* out = (float*)d_out;

    if ((nbatch & 3) == 0) {
        const int nwarps = (nbatch + BPW - 1) / BPW;   // 12 batches per warp
        const int blocks = (nwarps + 3) / 4;           // 4 warps per block
        epg_main<<<blocks, 128>>>(flip, phases, T1, T2, B0, B1, TRp, out,
                                  nbatch, nwarps);
    } else {
        const int blocks = (nbatch + 7) / 8;
        epg_simple<<<blocks, 256>>>(flip, phases, T1, T2, B0, B1, TRp, out, nbatch);
    }
}